// round 10
// baseline (speedup 1.0000x reference)
#include <cuda_runtime.h>
#include <cuda_bf16.h>
#include <cstdint>
#include <math.h>

// ============================================================================
// AdaptiveLoss, bf16 mma.sync. Round 8 (resubmit — infra failure last round):
//  - R7 structure (512 thr, 16 warps, 32x64 warp tiles, 3-stage cp.async,
//    A-resident batching, FULL-tile templates)
//  - NEW: register double-buffered fragment pipeline inside the K-chunk
//    (load ks+1 frags while computing ks) to hide LDSM latency.
// ============================================================================

#define B_ROWS 1024
#define ROWB   144
#define ACHUNK 18432            // 128 rows * 144B
#define BCHUNK 36864            // 256 rows * 144B
#define BBASE  73728            // after up to 4 resident (or 3 stream) A chunks
#define STAGEOFF 184320         // epilogue scratch (4KB)
#define SMEM_SZ  188416

// 256-col LSE chunks: head 40, c0 40, c1 79, c2 157, c3 79
__device__ const int d_chunks[5] = {40, 40, 79, 157, 79};
__device__ const int d_pbase[5]  = {0, 40960, 81920, 162816, 323584};
#define PM_TOTAL 404480

__device__ float g_pm[PM_TOTAL];
__device__ float g_ps[PM_TOTAL];
__device__ float g_lse[5 * B_ROWS];
__device__ float g_tail[B_ROWS * 4];
__device__ float g_num[B_ROWS];
__device__ float g_den[B_ROWS];
__device__ int   g_flags[2];

__device__ __nv_bfloat16 bf_feat[B_ROWS * 1024];
__device__ __nv_bfloat16 bf_headW[10244096];
__device__ __nv_bfloat16 bf_out0[5120000];
__device__ __nv_bfloat16 bf_out1[5120000];
__device__ __nv_bfloat16 bf_out2[5120000];
__device__ __nv_bfloat16 bf_out3[1280000];
__device__ __nv_bfloat16 bf_proj0[512 * 1024];
__device__ __nv_bfloat16 bf_proj1[256 * 1024];
__device__ __nv_bfloat16 bf_proj2[128 * 1024];
__device__ __nv_bfloat16 bf_proj3[64 * 1024];
__device__ __nv_bfloat16 bf_h0[B_ROWS * 512];
__device__ __nv_bfloat16 bf_h1[B_ROWS * 256];
__device__ __nv_bfloat16 bf_h2[B_ROWS * 128];
__device__ __nv_bfloat16 bf_h3[B_ROWS * 64];

// ---------------------------------------------------------------- PTX helpers
__device__ __forceinline__ uint32_t smem_u32(const void* p) {
    uint32_t a;
    asm("{ .reg .u64 t; cvta.to.shared.u64 t, %1; cvt.u32.u64 %0, t; }"
        : "=r"(a) : "l"(p));
    return a;
}
__device__ __forceinline__ void cp16(uint32_t dst, const void* src) {
    asm volatile("cp.async.cg.shared.global [%0], [%1], 16;"
                 :: "r"(dst), "l"(src) : "memory");
}
__device__ __forceinline__ void cp16p(uint32_t dst, const void* src, int szbytes) {
    asm volatile("cp.async.cg.shared.global [%0], [%1], 16, %2;"
                 :: "r"(dst), "l"(src), "r"(szbytes) : "memory");
}
#define CP_COMMIT() asm volatile("cp.async.commit_group;" ::: "memory")
#define CP_WAIT1()  asm volatile("cp.async.wait_group 1;" ::: "memory")

__device__ __forceinline__ void ldsm_x4(uint32_t* r, uint32_t addr) {
    asm volatile("ldmatrix.sync.aligned.m8n8.x4.shared.b16 {%0,%1,%2,%3}, [%4];"
                 : "=r"(r[0]), "=r"(r[1]), "=r"(r[2]), "=r"(r[3]) : "r"(addr));
}
__device__ __forceinline__ void mma_bf16(float* c, const uint32_t* a,
                                         const uint32_t* b) {
    asm volatile(
        "mma.sync.aligned.m16n8k16.row.col.f32.bf16.bf16.f32 "
        "{%0,%1,%2,%3}, {%4,%5,%6,%7}, {%8,%9}, {%0,%1,%2,%3};"
        : "+f"(c[0]), "+f"(c[1]), "+f"(c[2]), "+f"(c[3])
        : "r"(a[0]), "r"(a[1]), "r"(a[2]), "r"(a[3]), "r"(b[0]), "r"(b[1]));
}

// ---- 32x64 warp-tile compute over one 64-K chunk, frag-pipelined ------------
__device__ __forceinline__ void frag_load(uint32_t aB, uint32_t bB,
    uint32_t aRowOff, uint32_t bRowOff, int warpN, int ks,
    uint32_t (&af)[2][4], uint32_t (&bf4)[4][4])
{
#pragma unroll
    for (int mt = 0; mt < 2; mt++)
        ldsm_x4(af[mt], aB + aRowOff + mt * (16 * ROWB) + ks * 32);
#pragma unroll
    for (int p = 0; p < 4; p++)
        ldsm_x4(bf4[p], bB + (warpN * 64 + p * 16) * ROWB + bRowOff + ks * 32);
}

__device__ __forceinline__ void mma_tile(uint32_t aB, uint32_t bB,
    uint32_t aRowOff, uint32_t bRowOff, int warpN, float (&acc)[2][8][4])
{
    uint32_t af[2][2][4], bf4[2][4][4];
    frag_load(aB, bB, aRowOff, bRowOff, warpN, 0, af[0], bf4[0]);
#pragma unroll
    for (int ks = 0; ks < 4; ks++) {
        const int cur = ks & 1, nxt = cur ^ 1;
        if (ks < 3)
            frag_load(aB, bB, aRowOff, bRowOff, warpN, ks + 1, af[nxt], bf4[nxt]);
#pragma unroll
        for (int mt = 0; mt < 2; mt++)
#pragma unroll
            for (int nt = 0; nt < 8; nt++)
                mma_bf16(acc[mt][nt], af[cur][mt],
                         &bf4[cur][nt >> 1][(nt & 1) * 2]);
    }
}

// ---- fused online-LSE epilogue for one 256-col ytile ------------------------
template <bool FULL>
__device__ __forceinline__ void epi_lse(float (&acc)[2][8][4], int N,
    int rowBase, int colBase, int sel, int ytile, char* stage,
    int warpM, int warpN, int lane, int tid)
{
    float* smM = (float*)stage;
    float* smS = (float*)stage + 512;
#pragma unroll
    for (int mt = 0; mt < 2; mt++)
#pragma unroll
        for (int hf = 0; hf < 2; hf++) {
            const int rl = warpM * 32 + mt * 16 + (lane >> 2) + hf * 8;
            const int rg = rowBase + rl;
            float m = -INFINITY, s = 0.f;
            if (FULL) {
#pragma unroll
                for (int nt = 0; nt < 8; nt++)
#pragma unroll
                    for (int b2 = 0; b2 < 2; b2++)
                        m = fmaxf(m, acc[mt][nt][hf * 2 + b2]);
#pragma unroll
                for (int nt = 0; nt < 8; nt++)
#pragma unroll
                    for (int b2 = 0; b2 < 2; b2++)
                        s += __expf(acc[mt][nt][hf * 2 + b2] - m);
            } else {
#pragma unroll
                for (int nt = 0; nt < 8; nt++)
#pragma unroll
                    for (int b2 = 0; b2 < 2; b2++) {
                        const int cc = colBase + warpN * 64 + nt * 8
                                     + (lane & 3) * 2 + b2;
                        if (cc < N) m = fmaxf(m, acc[mt][nt][hf * 2 + b2]);
                    }
                if (m > -INFINITY) {
#pragma unroll
                    for (int nt = 0; nt < 8; nt++)
#pragma unroll
                        for (int b2 = 0; b2 < 2; b2++) {
                            const int cc = colBase + warpN * 64 + nt * 8
                                         + (lane & 3) * 2 + b2;
                            if (cc < N) {
                                const float v = acc[mt][nt][hf * 2 + b2];
                                s += __expf(v - m);
                                if (sel == 0 && cc >= 10000)
                                    g_tail[rg * 4 + (cc - 10000)] = v;
                            }
                        }
                }
            }
#pragma unroll
            for (int o = 1; o <= 2; o <<= 1) {
                const float mo = __shfl_xor_sync(0xffffffffu, m, o);
                const float so = __shfl_xor_sync(0xffffffffu, s, o);
                const float M2 = fmaxf(m, mo);
                if (M2 == -INFINITY) { m = M2; s = 0.f; }
                else { s = s * __expf(m - M2) + so * __expf(mo - M2); m = M2; }
            }
            if ((lane & 3) == 0) {
                smM[rl * 4 + warpN] = m;
                smS[rl * 4 + warpN] = s;
            }
        }
    __syncthreads();
    if (tid < 128) {
        float m = -INFINITY, s = 0.f;
#pragma unroll
        for (int w = 0; w < 4; w++) {
            const float mo = smM[tid * 4 + w], so = smS[tid * 4 + w];
            const float M2 = fmaxf(m, mo);
            if (M2 == -INFINITY) { m = M2; s = 0.f; }
            else { s = s * __expf(m - M2) + so * __expf(mo - M2); m = M2; }
        }
        const int chunks = d_chunks[sel];
        const size_t o = d_pbase[sel] + (size_t)(rowBase + tid) * chunks + ytile;
        g_pm[o] = m; g_ps[o] = s;
    }
    __syncthreads();
}

// ============================================================================
// Streaming GEMM: 3-stage pipeline, one sync per chunk.  K>=512 (nch>=8).
// ============================================================================
template <int MODE, bool FULL>
__device__ __forceinline__ void gemm_stream(
    const __nv_bfloat16* __restrict__ A, const __nv_bfloat16* __restrict__ W,
    __nv_bfloat16* __restrict__ Cb, int N, int K,
    int rowBase, int colBase, int sel, int ytile, char* smem)
{
    const uint32_t sb = smem_u32(smem);
    const int tid = threadIdx.x, lane = tid & 31, wid = tid >> 5;
    const int warpM = wid & 3, warpN = wid >> 2;

    float acc[2][8][4];
#pragma unroll
    for (int i = 0; i < 2; i++)
#pragma unroll
        for (int j = 0; j < 8; j++)
#pragma unroll
            for (int k = 0; k < 4; k++) acc[i][j][k] = 0.f;

    const uint32_t aRowOff =
        (uint32_t)((warpM * 32 + ((lane >> 3) & 1) * 8 + (lane & 7)) * ROWB
                   + (lane >> 4) * 16);
    const uint32_t bRowOff =
        (uint32_t)((((lane >> 4) & 1) * 8 + (lane & 7)) * ROWB
                   + ((lane >> 3) & 1) * 16);

    auto load_chunk = [&](int c, int buf) {
        const int k0 = c * 64;
        const uint32_t aB = sb + buf * ACHUNK;
        const uint32_t bB = sb + BBASE + buf * BCHUNK;
#pragma unroll
        for (int i = 0; i < 2; i++) {                 // A: 1024 units
            const int t = tid + i * 512, r = t >> 3, q = t & 7;
            cp16(aB + r * ROWB + q * 16,
                 A + (size_t)(rowBase + r) * K + k0 + q * 8);
        }
#pragma unroll
        for (int i = 0; i < 4; i++) {                 // B: 2048 units
            const int t = tid + i * 512, r = t >> 3, q = t & 7;
            if (FULL) {
                cp16(bB + r * ROWB + q * 16,
                     W + (size_t)(colBase + r) * K + k0 + q * 8);
            } else {
                const int n = colBase + r;
                const int ok = (n < N) ? 16 : 0;
                cp16p(bB + r * ROWB + q * 16,
                      W + (size_t)(ok ? n : 0) * K + k0 + q * 8, ok);
            }
        }
    };

    const int nch = K >> 6;
    load_chunk(0, 0);
    CP_COMMIT();
    if (nch > 1) load_chunk(1, 1);
    CP_COMMIT();
    int buf = 0, nbuf = 2;
    for (int c = 0; c < nch; c++) {
        CP_WAIT1();
        __syncthreads();
        if (c + 2 < nch) { load_chunk(c + 2, nbuf); }
        CP_COMMIT();
        mma_tile(sb + buf * ACHUNK, sb + BBASE + buf * BCHUNK,
                 aRowOff, bRowOff, warpN, acc);
        buf = (buf == 2) ? 0 : buf + 1;
        nbuf = (nbuf == 2) ? 0 : nbuf + 1;
    }
    __syncthreads();

    if (MODE == 0) {
#pragma unroll
        for (int mt = 0; mt < 2; mt++)
#pragma unroll
            for (int nt = 0; nt < 8; nt++)
#pragma unroll
                for (int rg = 0; rg < 4; rg++) {
                    const int r = rowBase + warpM * 32 + mt * 16 + (lane >> 2)
                                + (rg >> 1) * 8;
                    const int cc = colBase + warpN * 64 + nt * 8
                                 + (lane & 3) * 2 + (rg & 1);
                    if (cc < N)
                        Cb[(size_t)r * N + cc] = __float2bfloat16(acc[mt][nt][rg]);
                }
    } else {
        epi_lse<FULL>(acc, N, rowBase, colBase, sel, ytile, smem + STAGEOFF,
                      warpM, warpN, lane, tid);
    }
}

// ============================================================================
// A-resident GEMM: A (128 x K, K<=256) loaded once; streams B for `cnt`
// consecutive 256-col ytiles through one continuous 3-stage pipeline.
// ============================================================================
__device__ __forceinline__ void gemm_resident(
    const __nv_bfloat16* __restrict__ A, const __nv_bfloat16* __restrict__ W,
    int N, int K, int rowBase, int y0, int cnt, int sel, char* smem)
{
    const uint32_t sb = smem_u32(smem);
    const int tid = threadIdx.x, lane = tid & 31, wid = tid >> 5;
    const int warpM = wid & 3, warpN = wid >> 2;
    const int nch = K >> 6;

    const uint32_t aRowOff =
        (uint32_t)((warpM * 32 + ((lane >> 3) & 1) * 8 + (lane & 7)) * ROWB
                   + (lane >> 4) * 16);
    const uint32_t bRowOff =
        (uint32_t)((((lane >> 4) & 1) * 8 + (lane & 7)) * ROWB
                   + ((lane >> 3) & 1) * 16);

    // resident A: all chunks (part of first commit group)
    for (int u = tid; u < nch * 1024; u += 512) {
        const int c = u >> 10, t = u & 1023, r = t >> 3, q = t & 7;
        cp16(sb + c * ACHUNK + r * ROWB + q * 16,
             A + (size_t)(rowBase + r) * K + c * 64 + q * 8);
    }

    auto load_b = [&](int i, int buf) {   // i-th B chunk, flat (tile, chunk)
        const int t = i / nch, c = i - t * nch;
        const int colBase = (y0 + t) * 256;
        const int k0 = c * 64;
        const uint32_t bB = sb + BBASE + buf * BCHUNK;
        if (colBase + 256 <= N) {
#pragma unroll
            for (int j = 0; j < 4; j++) {
                const int tt = tid + j * 512, r = tt >> 3, q = tt & 7;
                cp16(bB + r * ROWB + q * 16,
                     W + (size_t)(colBase + r) * K + k0 + q * 8);
            }
        } else {
#pragma unroll
            for (int j = 0; j < 4; j++) {
                const int tt = tid + j * 512, r = tt >> 3, q = tt & 7;
                const int n = colBase + r;
                const int ok = (n < N) ? 16 : 0;
                cp16p(bB + r * ROWB + q * 16,
                      W + (size_t)(ok ? n : 0) * K + k0 + q * 8, ok);
            }
        }
    };

    const int total = cnt * nch;
    load_b(0, 0);
    CP_COMMIT();
    if (total > 1) load_b(1, 1);
    CP_COMMIT();

    float acc[2][8][4];
#pragma unroll
    for (int i = 0; i < 2; i++)
#pragma unroll
        for (int j = 0; j < 8; j++)
#pragma unroll
            for (int k = 0; k < 4; k++) acc[i][j][k] = 0.f;

    int buf = 0, nbuf = 2;
    for (int i = 0; i < total; i++) {
        const int t = i / nch, c = i - t * nch;
        CP_WAIT1();
        __syncthreads();
        if (i + 2 < total) { load_b(i + 2, nbuf); }
        CP_COMMIT();
        mma_tile(sb + c * ACHUNK, sb + BBASE + buf * BCHUNK,
                 aRowOff, bRowOff, warpN, acc);
        buf = (buf == 2) ? 0 : buf + 1;
        nbuf = (nbuf == 2) ? 0 : nbuf + 1;
        if (c == nch - 1) {
            const int colBase = (y0 + t) * 256;
            if (colBase + 256 <= N)
                epi_lse<true>(acc, N, rowBase, colBase, sel, y0 + t,
                              smem + STAGEOFF, warpM, warpN, lane, tid);
            else
                epi_lse<false>(acc, N, rowBase, colBase, sel, y0 + t,
                               smem + STAGEOFF, warpM, warpN, lane, tid);
#pragma unroll
            for (int a = 0; a < 2; a++)
#pragma unroll
                for (int b = 0; b < 8; b++)
#pragma unroll
                    for (int k = 0; k < 4; k++) acc[a][b][k] = 0.f;
        }
    }
}

// ============================================================================
// launch 2: head (streaming LSE) + 4 proj GEMMs.  y in [0,45)
// ============================================================================
__global__ __launch_bounds__(512, 1)
void head_proj_kernel()
{
    extern __shared__ char smem[];
    const int y = blockIdx.y;
    const int rowBase = blockIdx.x * 128;
    if (y < 39) {
        gemm_stream<1, true>(bf_feat, bf_headW, nullptr, 10004, 1024,
                             rowBase, y * 256, 0, y, smem);
    } else if (y == 39) {
        gemm_stream<1, false>(bf_feat, bf_headW, nullptr, 10004, 1024,
                              rowBase, y * 256, 0, y, smem);
    } else {
        const __nv_bfloat16* W; __nv_bfloat16* Cb; int N, colBase = 0;
        if (y < 42)      { W = bf_proj0; Cb = bf_h0; N = 512; colBase = (y - 40) * 256; }
        else if (y == 42){ W = bf_proj1; Cb = bf_h1; N = 256; }
        else if (y == 43){ W = bf_proj2; Cb = bf_h2; N = 128; }
        else             { W = bf_proj3; Cb = bf_h3; N = 64; }
        if (colBase + 256 <= N)
            gemm_stream<0, true>(bf_feat, W, Cb, N, 1024, rowBase, colBase,
                                 -1, 0, smem);
        else
            gemm_stream<0, false>(bf_feat, W, Cb, N, 1024, rowBase, colBase,
                                  -1, 0, smem);
    }
}

// ============================================================================
// launch 3: clusters.  y in [0,130): 0..39 c0(K=512, stream)
//   | 40..79 c1(K=256,g2) | 80..119 c2(K=128,g4) | 120..129 c3(K=64,g8)
// ============================================================================
__global__ __launch_bounds__(512, 1)
void cluster_kernel()
{
    extern __shared__ char smem[];
    const int y = blockIdx.y;
    const int rowBase = blockIdx.x * 128;
    if (y < 40) {
        if (y < 39)
            gemm_stream<1, true>(bf_h0, bf_out0, nullptr, 10000, 512,
                                 rowBase, y * 256, 1, y, smem);
        else
            gemm_stream<1, false>(bf_h0, bf_out0, nullptr, 10000, 512,
                                  rowBase, y * 256, 1, y, smem);
    } else if (y < 80) {
        const int y0 = (y - 40) * 2, cnt = (79 - y0 < 2) ? (79 - y0) : 2;
        gemm_resident(bf_h1, bf_out1, 20000, 256, rowBase, y0, cnt, 2, smem);
    } else if (y < 120) {
        const int y0 = (y - 80) * 4, cnt = (157 - y0 < 4) ? (157 - y0) : 4;
        gemm_resident(bf_h2, bf_out2, 40000, 128, rowBase, y0, cnt, 3, smem);
    } else {
        const int y0 = (y - 120) * 8, cnt = (79 - y0 < 8) ? (79 - y0) : 8;
        gemm_resident(bf_h3, bf_out3, 20000, 64, rowBase, y0, cnt, 4, smem);
    }
}

// ---------------------------------------------------------------- cvt (fused)
__global__ void cvt_all(const float* s0, const float* s1, const float* s2,
                        const float* s3, const float* s4, const float* s5,
                        const float* s6, const float* s7, const float* s8,
                        const float* s9)
{
    const int cum[11] = {0, 262144, 2823168, 4103168, 5383168, 6663168,
                         6983168, 7114240, 7179776, 7212544, 7228928};
    for (int i = blockIdx.x * blockDim.x + threadIdx.x; i < 7228928;
         i += gridDim.x * blockDim.x) {
        int seg = 0;
#pragma unroll
        for (int t = 1; t < 10; t++) seg += (i >= cum[t]);
        const int off = i - cum[seg];
        const float* src;
        __nv_bfloat16* dst;
        switch (seg) {
            case 0: src = s0; dst = bf_feat;  break;
            case 1: src = s1; dst = bf_headW; break;
            case 2: src = s2; dst = bf_out0;  break;
            case 3: src = s3; dst = bf_out1;  break;
            case 4: src = s4; dst = bf_out2;  break;
            case 5: src = s5; dst = bf_out3;  break;
            case 6: src = s6; dst = bf_proj0; break;
            case 7: src = s7; dst = bf_proj1; break;
            case 8: src = s8; dst = bf_proj2; break;
            default: src = s9; dst = bf_proj3; break;
        }
        const float4 v = ((const float4*)src)[off];
        __nv_bfloat162* p = (__nv_bfloat162*)dst + off * 2;
        p[0] = __floats2bfloat162_rn(v.x, v.y);
        p[1] = __floats2bfloat162_rn(v.z, v.w);
    }
}

// ---------------------------------------------------------------- small kernels
__global__ void init_kernel(const void* tgt, const void* msk) {
    const int tid = threadIdx.x;
    if (tid < B_ROWS) { g_num[tid] = 0.f; g_den[tid] = 0.f; }
    if (tid == 0) {
        const int* ti = (const int*)tgt;
        int nz = 0;
        for (int j = 0; j < 128; j++) nz += (ti[2 * j + 1] != 0);
        g_flags[0] = (nz <= 8) ? 1 : 0;
        const unsigned int* mw = (const unsigned int*)msk;
        int looks_i32 = 1;
        for (int j = 0; j < 64; j++) if (mw[j] > 255u) looks_i32 = 0;
        g_flags[1] = looks_i32;
    }
}

__global__ void combine_kernel() {
    int row = blockIdx.x, mat = blockIdx.y, lane = threadIdx.x;
    int chunks = d_chunks[mat];
    const float* pm = g_pm + d_pbase[mat] + (size_t)row * chunks;
    const float* ps = g_ps + d_pbase[mat] + (size_t)row * chunks;
    float m = -INFINITY, s = 0.f;
    for (int c = lane; c < chunks; c += 32) {
        float mo = pm[c], so = ps[c];
        float M2 = fmaxf(m, mo);
        if (M2 == -INFINITY) { m = M2; s = 0.f; }
        else { s = s * __expf(m - M2) + so * __expf(mo - M2); m = M2; }
    }
    for (int o = 1; o < 32; o <<= 1) {
        float mo = __shfl_xor_sync(0xffffffffu, m, o);
        float so = __shfl_xor_sync(0xffffffffu, s, o);
        float M2 = fmaxf(m, mo);
        if (M2 == -INFINITY) { m = M2; s = 0.f; }
        else { s = s * __expf(m - M2) + so * __expf(mo - M2); m = M2; }
    }
    if (lane == 0) g_lse[mat * B_ROWS + row] = m + logf(s);
}

// warp per target; bf16 operands (L2-warm), fp32 accumulate
__global__ void loss_kernel(const float* __restrict__ discard,
                            const void* __restrict__ tgt,
                            const void* __restrict__ msk)
{
    int gwarp = (blockIdx.x * blockDim.x + threadIdx.x) >> 5;
    int lane  = threadIdx.x & 31;
    if (gwarp >= B_ROWS * 128) return;
    int b = gwarp >> 7;

    long long v;
    if (g_flags[0]) v = ((const long long*)tgt)[gwarp];
    else            v = (long long)((const int*)tgt)[gwarp];

    float mk;
    if (g_flags[1]) mk = (((const int*)msk)[gwarp] != 0) ? 1.f : 0.f;
    else            mk = (((const unsigned char*)msk)[gwarp] != 0) ? 1.f : 0.f;

    const __nv_bfloat16 *a, *w;
    int Kd; float lse, extra;
    float hlse = g_lse[b];
    if (v < 10000) {
        a = bf_feat + (size_t)b * 1024; w = bf_headW + (size_t)v * 1024;
        Kd = 1024; lse = hlse; extra = 0.f;
    } else if (v < 20000) {
        a = bf_h0 + (size_t)b * 512; w = bf_out0 + (size_t)(v - 10000) * 512;
        Kd = 512; lse = g_lse[1 * B_ROWS + b]; extra = g_tail[b * 4 + 0] - hlse;
    } else if (v < 40000) {
        a = bf_h1 + (size_t)b * 256; w = bf_out1 + (size_t)(v - 20000) * 256;
        Kd = 256; lse = g_lse[2 * B_ROWS + b]; extra = g_tail[b * 4 + 1] - hlse;
    } else if (v < 80000) {
        a = bf_h2 + (size_t)b * 128; w = bf_out2 + (size_t)(v - 40000) * 128;
        Kd = 128; lse = g_lse[3 * B_ROWS + b]; extra = g_tail[b * 4 + 2] - hlse;
    } else {
        a = bf_h3 + (size_t)b * 64; w = bf_out3 + (size_t)(v - 80000) * 64;
        Kd = 64; lse = g_lse[4 * B_ROWS + b]; extra = g_tail[b * 4 + 3] - hlse;
    }

    float dot = 0.f;
    for (int k = lane * 8; k < Kd; k += 256) {
        const uint4 av = *(const uint4*)(a + k);
        const uint4 wv = *(const uint4*)(w + k);
        const uint32_t aw[4] = {av.x, av.y, av.z, av.w};
        const uint32_t ww[4] = {wv.x, wv.y, wv.z, wv.w};
#pragma unroll
        for (int j = 0; j < 4; j++) {
            const float2 af2 = __bfloat1622float2(*(const __nv_bfloat162*)&aw[j]);
            const float2 wf2 = __bfloat1622float2(*(const __nv_bfloat162*)&ww[j]);
            dot += af2.x * wf2.x + af2.y * wf2.y;
        }
    }
#pragma unroll
    for (int o = 16; o >= 1; o >>= 1) dot += __shfl_xor_sync(0xffffffffu, dot, o);

    if (lane == 0) {
        float lp = dot - lse + extra;
        float wt = (1.f - discard[v]) * mk;
        atomicAdd(&g_num[b], -lp * wt);
        atomicAdd(&g_den[b], wt);
    }
}

__global__ void final_kernel(float* out) {
    __shared__ float red[256];
    float s = 0.f;
    for (int i = threadIdx.x; i < B_ROWS; i += 256) s += g_num[i] / g_den[i];
    red[threadIdx.x] = s;
    __syncthreads();
    for (int o = 128; o >= 1; o >>= 1) {
        if (threadIdx.x < o) red[threadIdx.x] += red[threadIdx.x + o];
        __syncthreads();
    }
    if (threadIdx.x == 0)
        out[0] = (float)((double)red[0] / (1024.0 + 1e-5));
}

// ============================================================================
extern "C" void kernel_launch(void* const* d_in, const int* in_sizes, int n_in,
                              void* d_out, int out_size)
{
    const float* feat    = (const float*)d_in[0];
    const float* headW   = (const float*)d_in[1];
    const float* proj0   = (const float*)d_in[2];
    const float* out0    = (const float*)d_in[3];
    const float* proj1   = (const float*)d_in[4];
    const float* out1    = (const float*)d_in[5];
    const float* proj2   = (const float*)d_in[6];
    const float* out2    = (const float*)d_in[7];
    const float* proj3   = (const float*)d_in[8];
    const float* out3    = (const float*)d_in[9];
    const float* discard = (const float*)d_in[10];
    const void*  tgt     = d_in[11];
    const void*  msk     = d_in[12];
    float* out = (float*)d_out;

    cudaFuncSetAttribute(head_proj_kernel,
                         cudaFuncAttributeMaxDynamicSharedMemorySize, SMEM_SZ);
    cudaFuncSetAttribute(cluster_kernel,
                         cudaFuncAttributeMaxDynamicSharedMemorySize, SMEM_SZ);

    init_kernel<<<1, 1024>>>(tgt, msk);
    cvt_all<<<4096, 256>>>(feat, headW, out0, out1, out2, out3,
                           proj0, proj1, proj2, proj3);
    head_proj_kernel<<<dim3(8, 45),  512, SMEM_SZ>>>();
    cluster_kernel<<<dim3(8, 130),   512, SMEM_SZ>>>();
    combine_kernel<<<dim3(1024, 5), 32>>>();
    loss_kernel<<<16384, 256>>>(discard, tgt, msk);
    final_kernel<<<1, 256>>>(out);
}

// round 11
// speedup vs baseline: 1.1175x; 1.1175x over previous
#include <cuda_runtime.h>
#include <cuda_bf16.h>
#include <cstdint>
#include <math.h>

// ============================================================================
// AdaptiveLoss, bf16 mma.sync. Round 11:
//  - 2 CTAs/SM: 256 thr / 8 warps, CTA tile 128x128, warp tile 32x64,
//    __launch_bounds__(256,2); smem <= 114688/CTA so two CTAs co-reside.
//  - stream GEMM (3-stage A+B) for K>=256; A-resident (3 B-bufs) for K<=128.
//  - simple frag loads (R7 scheme — measured better than double-buffer).
// ============================================================================

#define B_ROWS 1024
#define ROWB   144
#define ACHUNK 18432            // 128 rows * 144B
// stream: A bufs 0..2 at buf*ACHUNK, B bufs at 3*ACHUNK + buf*ACHUNK
#define BSTREAM 55296
// resident<NCH>: A chunks at c*ACHUNK, B bufs at NCH*ACHUNK + buf*ACHUNK
#define STAGEOFF 110592
#define SMEM_SZ  114688

// 128-col LSE chunks: head 79, c0 79, c1 157, c2 313, c3 157
__device__ const int d_chunks[5] = {79, 79, 157, 313, 157};
__device__ const int d_pbase[5]  = {0, 80896, 161792, 322560, 643072};
#define PM_TOTAL 803840

__device__ float g_pm[PM_TOTAL];
__device__ float g_ps[PM_TOTAL];
__device__ float g_lse[5 * B_ROWS];
__device__ float g_tail[B_ROWS * 4];
__device__ float g_num[B_ROWS];
__device__ float g_den[B_ROWS];
__device__ int   g_flags[2];

__device__ __nv_bfloat16 bf_feat[B_ROWS * 1024];
__device__ __nv_bfloat16 bf_headW[10244096];
__device__ __nv_bfloat16 bf_out0[5120000];
__device__ __nv_bfloat16 bf_out1[5120000];
__device__ __nv_bfloat16 bf_out2[5120000];
__device__ __nv_bfloat16 bf_out3[1280000];
__device__ __nv_bfloat16 bf_proj0[512 * 1024];
__device__ __nv_bfloat16 bf_proj1[256 * 1024];
__device__ __nv_bfloat16 bf_proj2[128 * 1024];
__device__ __nv_bfloat16 bf_proj3[64 * 1024];
__device__ __nv_bfloat16 bf_h0[B_ROWS * 512];
__device__ __nv_bfloat16 bf_h1[B_ROWS * 256];
__device__ __nv_bfloat16 bf_h2[B_ROWS * 128];
__device__ __nv_bfloat16 bf_h3[B_ROWS * 64];

// ---------------------------------------------------------------- PTX helpers
__device__ __forceinline__ uint32_t smem_u32(const void* p) {
    uint32_t a;
    asm("{ .reg .u64 t; cvta.to.shared.u64 t, %1; cvt.u32.u64 %0, t; }"
        : "=r"(a) : "l"(p));
    return a;
}
__device__ __forceinline__ void cp16(uint32_t dst, const void* src) {
    asm volatile("cp.async.cg.shared.global [%0], [%1], 16;"
                 :: "r"(dst), "l"(src) : "memory");
}
__device__ __forceinline__ void cp16p(uint32_t dst, const void* src, int szbytes) {
    asm volatile("cp.async.cg.shared.global [%0], [%1], 16, %2;"
                 :: "r"(dst), "l"(src), "r"(szbytes) : "memory");
}
#define CP_COMMIT() asm volatile("cp.async.commit_group;" ::: "memory")
#define CP_WAIT1()  asm volatile("cp.async.wait_group 1;" ::: "memory")

__device__ __forceinline__ void ldsm_x4(uint32_t* r, uint32_t addr) {
    asm volatile("ldmatrix.sync.aligned.m8n8.x4.shared.b16 {%0,%1,%2,%3}, [%4];"
                 : "=r"(r[0]), "=r"(r[1]), "=r"(r[2]), "=r"(r[3]) : "r"(addr));
}
__device__ __forceinline__ void mma_bf16(float* c, const uint32_t* a,
                                         const uint32_t* b) {
    asm volatile(
        "mma.sync.aligned.m16n8k16.row.col.f32.bf16.bf16.f32 "
        "{%0,%1,%2,%3}, {%4,%5,%6,%7}, {%8,%9}, {%0,%1,%2,%3};"
        : "+f"(c[0]), "+f"(c[1]), "+f"(c[2]), "+f"(c[3])
        : "r"(a[0]), "r"(a[1]), "r"(a[2]), "r"(a[3]), "r"(b[0]), "r"(b[1]));
}

// ---- 32x64 warp-tile compute over one 64-K chunk (simple frags) -------------
__device__ __forceinline__ void mma_tile(uint32_t aB, uint32_t bB,
    uint32_t aRowOff, uint32_t bRowOff, int warpN, float (&acc)[2][8][4])
{
#pragma unroll
    for (int ks = 0; ks < 4; ks++) {
        uint32_t af[2][4], bf4[4][4];
#pragma unroll
        for (int mt = 0; mt < 2; mt++)
            ldsm_x4(af[mt], aB + aRowOff + mt * (16 * ROWB) + ks * 32);
#pragma unroll
        for (int p = 0; p < 4; p++)
            ldsm_x4(bf4[p], bB + (warpN * 64 + p * 16) * ROWB + bRowOff + ks * 32);
#pragma unroll
        for (int mt = 0; mt < 2; mt++)
#pragma unroll
            for (int nt = 0; nt < 8; nt++)
                mma_bf16(acc[mt][nt], af[mt], &bf4[nt >> 1][(nt & 1) * 2]);
    }
}

// ---- fused online-LSE epilogue for one 128-col ytile ------------------------
// 8 warps: warpM in [0,4) covers rows, warpN in [0,2) covers 64-col halves.
template <bool FULL>
__device__ __forceinline__ void epi_lse(float (&acc)[2][8][4], int N,
    int rowBase, int colBase, int sel, int ytile, char* stage,
    int warpM, int warpN, int lane, int tid)
{
    float* smM = (float*)stage;           // [128 rows][2 warpN]
    float* smS = (float*)stage + 256;
#pragma unroll
    for (int mt = 0; mt < 2; mt++)
#pragma unroll
        for (int hf = 0; hf < 2; hf++) {
            const int rl = warpM * 32 + mt * 16 + (lane >> 2) + hf * 8;
            const int rg = rowBase + rl;
            float m = -INFINITY, s = 0.f;
            if (FULL) {
#pragma unroll
                for (int nt = 0; nt < 8; nt++)
#pragma unroll
                    for (int b2 = 0; b2 < 2; b2++)
                        m = fmaxf(m, acc[mt][nt][hf * 2 + b2]);
#pragma unroll
                for (int nt = 0; nt < 8; nt++)
#pragma unroll
                    for (int b2 = 0; b2 < 2; b2++)
                        s += __expf(acc[mt][nt][hf * 2 + b2] - m);
            } else {
#pragma unroll
                for (int nt = 0; nt < 8; nt++)
#pragma unroll
                    for (int b2 = 0; b2 < 2; b2++) {
                        const int cc = colBase + warpN * 64 + nt * 8
                                     + (lane & 3) * 2 + b2;
                        if (cc < N) m = fmaxf(m, acc[mt][nt][hf * 2 + b2]);
                    }
                if (m > -INFINITY) {
#pragma unroll
                    for (int nt = 0; nt < 8; nt++)
#pragma unroll
                        for (int b2 = 0; b2 < 2; b2++) {
                            const int cc = colBase + warpN * 64 + nt * 8
                                         + (lane & 3) * 2 + b2;
                            if (cc < N) {
                                const float v = acc[mt][nt][hf * 2 + b2];
                                s += __expf(v - m);
                                if (sel == 0 && cc >= 10000)
                                    g_tail[rg * 4 + (cc - 10000)] = v;
                            }
                        }
                }
            }
#pragma unroll
            for (int o = 1; o <= 2; o <<= 1) {
                const float mo = __shfl_xor_sync(0xffffffffu, m, o);
                const float so = __shfl_xor_sync(0xffffffffu, s, o);
                const float M2 = fmaxf(m, mo);
                if (M2 == -INFINITY) { m = M2; s = 0.f; }
                else { s = s * __expf(m - M2) + so * __expf(mo - M2); m = M2; }
            }
            if ((lane & 3) == 0) {
                smM[rl * 2 + warpN] = m;
                smS[rl * 2 + warpN] = s;
            }
        }
    __syncthreads();
    if (tid < 128) {
        const float m0 = smM[tid * 2 + 0], s0 = smS[tid * 2 + 0];
        const float m1 = smM[tid * 2 + 1], s1 = smS[tid * 2 + 1];
        const float M2 = fmaxf(m0, m1);
        float mm, ss;
        if (M2 == -INFINITY) { mm = M2; ss = 0.f; }
        else { ss = s0 * __expf(m0 - M2) + s1 * __expf(m1 - M2); mm = M2; }
        const int chunks = d_chunks[sel];
        const size_t o = d_pbase[sel] + (size_t)(rowBase + tid) * chunks + ytile;
        g_pm[o] = mm; g_ps[o] = ss;
    }
    __syncthreads();
}

// ============================================================================
// Streaming GEMM: 3-stage pipeline, one sync per chunk.  K>=256 (nch>=4).
// ============================================================================
template <int MODE, bool FULL>
__device__ __forceinline__ void gemm_stream(
    const __nv_bfloat16* __restrict__ A, const __nv_bfloat16* __restrict__ W,
    __nv_bfloat16* __restrict__ Cb, int N, int K,
    int rowBase, int colBase, int sel, int ytile, char* smem)
{
    const uint32_t sb = smem_u32(smem);
    const int tid = threadIdx.x, lane = tid & 31, wid = tid >> 5;
    const int warpM = wid & 3, warpN = wid >> 2;

    float acc[2][8][4];
#pragma unroll
    for (int i = 0; i < 2; i++)
#pragma unroll
        for (int j = 0; j < 8; j++)
#pragma unroll
            for (int k = 0; k < 4; k++) acc[i][j][k] = 0.f;

    const uint32_t aRowOff =
        (uint32_t)((warpM * 32 + ((lane >> 3) & 1) * 8 + (lane & 7)) * ROWB
                   + (lane >> 4) * 16);
    const uint32_t bRowOff =
        (uint32_t)((((lane >> 4) & 1) * 8 + (lane & 7)) * ROWB
                   + ((lane >> 3) & 1) * 16);

    auto load_chunk = [&](int c, int buf) {
        const int k0 = c * 64;
        const uint32_t aB = sb + buf * ACHUNK;
        const uint32_t bB = sb + BSTREAM + buf * ACHUNK;
#pragma unroll
        for (int i = 0; i < 4; i++) {                 // A: 1024 units
            const int t = tid + i * 256, r = t >> 3, q = t & 7;
            cp16(aB + r * ROWB + q * 16,
                 A + (size_t)(rowBase + r) * K + k0 + q * 8);
        }
#pragma unroll
        for (int i = 0; i < 4; i++) {                 // B: 1024 units
            const int t = tid + i * 256, r = t >> 3, q = t & 7;
            if (FULL) {
                cp16(bB + r * ROWB + q * 16,
                     W + (size_t)(colBase + r) * K + k0 + q * 8);
            } else {
                const int n = colBase + r;
                const int ok = (n < N) ? 16 : 0;
                cp16p(bB + r * ROWB + q * 16,
                      W + (size_t)(ok ? n : 0) * K + k0 + q * 8, ok);
            }
        }
    };

    const int nch = K >> 6;
    load_chunk(0, 0);
    CP_COMMIT();
    load_chunk(1, 1);
    CP_COMMIT();
    int buf = 0, nbuf = 2;
    for (int c = 0; c < nch; c++) {
        CP_WAIT1();
        __syncthreads();
        if (c + 2 < nch) { load_chunk(c + 2, nbuf); }
        CP_COMMIT();
        mma_tile(sb + buf * ACHUNK, sb + BSTREAM + buf * ACHUNK,
                 aRowOff, bRowOff, warpN, acc);
        buf = (buf == 2) ? 0 : buf + 1;
        nbuf = (nbuf == 2) ? 0 : nbuf + 1;
    }
    __syncthreads();

    if (MODE == 0) {
#pragma unroll
        for (int mt = 0; mt < 2; mt++)
#pragma unroll
            for (int nt = 0; nt < 8; nt++)
#pragma unroll
                for (int rg = 0; rg < 4; rg++) {
                    const int r = rowBase + warpM * 32 + mt * 16 + (lane >> 2)
                                + (rg >> 1) * 8;
                    const int cc = colBase + warpN * 64 + nt * 8
                                 + (lane & 3) * 2 + (rg & 1);
                    if (cc < N)
                        Cb[(size_t)r * N + cc] = __float2bfloat16(acc[mt][nt][rg]);
                }
    } else {
        epi_lse<FULL>(acc, N, rowBase, colBase, sel, ytile, smem + STAGEOFF,
                      warpM, warpN, lane, tid);
    }
}

// ============================================================================
// A-resident GEMM (K<=128): A loaded once; streams B for `cnt` consecutive
// 128-col ytiles through one continuous pipeline (3 B buffers).
// ============================================================================
template <int NCH>
__device__ __forceinline__ void gemm_resident(
    const __nv_bfloat16* __restrict__ A, const __nv_bfloat16* __restrict__ W,
    int N, int rowBase, int y0, int cnt, int sel, char* smem)
{
    const uint32_t sb = smem_u32(smem);
    const int tid = threadIdx.x, lane = tid & 31, wid = tid >> 5;
    const int warpM = wid & 3, warpN = wid >> 2;
    const int K = NCH * 64;

    const uint32_t aRowOff =
        (uint32_t)((warpM * 32 + ((lane >> 3) & 1) * 8 + (lane & 7)) * ROWB
                   + (lane >> 4) * 16);
    const uint32_t bRowOff =
        (uint32_t)((((lane >> 4) & 1) * 8 + (lane & 7)) * ROWB
                   + ((lane >> 3) & 1) * 16);

    // resident A: all NCH chunks (part of first commit group)
#pragma unroll
    for (int u = tid; u < NCH * 1024; u += 256) {
        const int c = u >> 10, t = u & 1023, r = t >> 3, q = t & 7;
        cp16(sb + c * ACHUNK + r * ROWB + q * 16,
             A + (size_t)(rowBase + r) * K + c * 64 + q * 8);
    }

    auto load_b = [&](int i, int buf) {   // i-th B chunk, flat (tile, chunk)
        const int t = i / NCH, c = i - t * NCH;
        const int colBase = (y0 + t) * 128;
        const int k0 = c * 64;
        const uint32_t bB = sb + NCH * ACHUNK + buf * ACHUNK;
        if (colBase + 128 <= N) {
#pragma unroll
            for (int j = 0; j < 4; j++) {
                const int tt = tid + j * 256, r = tt >> 3, q = tt & 7;
                cp16(bB + r * ROWB + q * 16,
                     W + (size_t)(colBase + r) * K + k0 + q * 8);
            }
        } else {
#pragma unroll
            for (int j = 0; j < 4; j++) {
                const int tt = tid + j * 256, r = tt >> 3, q = tt & 7;
                const int n = colBase + r;
                const int ok = (n < N) ? 16 : 0;
                cp16p(bB + r * ROWB + q * 16,
                      W + (size_t)(ok ? n : 0) * K + k0 + q * 8, ok);
            }
        }
    };

    const int total = cnt * NCH;
    load_b(0, 0);
    CP_COMMIT();
    if (total > 1) load_b(1, 1);
    CP_COMMIT();

    float acc[2][8][4];
#pragma unroll
    for (int i = 0; i < 2; i++)
#pragma unroll
        for (int j = 0; j < 8; j++)
#pragma unroll
            for (int k = 0; k < 4; k++) acc[i][j][k] = 0.f;

    int buf = 0, nbuf = 2;
    for (int i = 0; i < total; i++) {
        const int t = i / NCH, c = i - t * NCH;
        CP_WAIT1();
        __syncthreads();
        if (i + 2 < total) { load_b(i + 2, nbuf); }
        CP_COMMIT();
        mma_tile(sb + c * ACHUNK, sb + NCH * ACHUNK + buf * ACHUNK,
                 aRowOff, bRowOff, warpN, acc);
        buf = (buf == 2) ? 0 : buf + 1;
        nbuf = (nbuf == 2) ? 0 : nbuf + 1;
        if (c == NCH - 1) {
            const int colBase = (y0 + t) * 128;
            if (colBase + 128 <= N)
                epi_lse<true>(acc, N, rowBase, colBase, sel, y0 + t,
                              smem + STAGEOFF, warpM, warpN, lane, tid);
            else
                epi_lse<false>(acc, N, rowBase, colBase, sel, y0 + t,
                               smem + STAGEOFF, warpM, warpN, lane, tid);
#pragma unroll
            for (int a = 0; a < 2; a++)
#pragma unroll
                for (int b = 0; b < 8; b++)
#pragma unroll
                    for (int k = 0; k < 4; k++) acc[a][b][k] = 0.f;
        }
    }
}

// ============================================================================
// launch 2: head (streaming LSE, 79 tiles) + proj tiles (8).  y in [0,87)
// ============================================================================
__global__ __launch_bounds__(256, 2)
void head_proj_kernel()
{
    extern __shared__ char smem[];
    const int y = blockIdx.y;
    const int rowBase = blockIdx.x * 128;
    if (y < 78) {
        gemm_stream<1, true>(bf_feat, bf_headW, nullptr, 10004, 1024,
                             rowBase, y * 128, 0, y, smem);
    } else if (y == 78) {
        gemm_stream<1, false>(bf_feat, bf_headW, nullptr, 10004, 1024,
                              rowBase, y * 128, 0, y, smem);
    } else {
        const __nv_bfloat16* W; __nv_bfloat16* Cb; int N, colBase;
        if (y < 83)      { W = bf_proj0; Cb = bf_h0; N = 512; colBase = (y - 79) * 128; }
        else if (y < 85) { W = bf_proj1; Cb = bf_h1; N = 256; colBase = (y - 83) * 128; }
        else if (y == 85){ W = bf_proj2; Cb = bf_h2; N = 128; colBase = 0; }
        else             { W = bf_proj3; Cb = bf_h3; N = 64;  colBase = 0; }
        if (colBase + 128 <= N)
            gemm_stream<0, true>(bf_feat, W, Cb, N, 1024, rowBase, colBase,
                                 -1, 0, smem);
        else
            gemm_stream<0, false>(bf_feat, W, Cb, N, 1024, rowBase, colBase,
                                  -1, 0, smem);
    }
}

// ============================================================================
// launch 3: clusters.  y in [0,335):
//   0..78    c0  K=512 stream   (79 tiles)
//   79..235  c1  K=256 stream   (157 tiles)
//   236..314 c2  K=128 resident (313 tiles, groups of 4)
//   315..334 c3  K=64  resident (157 tiles, groups of 8)
// ============================================================================
__global__ __launch_bounds__(256, 2)
void cluster_kernel()
{
    extern __shared__ char smem[];
    const int y = blockIdx.y;
    const int rowBase = blockIdx.x * 128;
    if (y < 79) {
        if (y < 78)
            gemm_stream<1, true>(bf_h0, bf_out0, nullptr, 10000, 512,
                                 rowBase, y * 128, 1, y, smem);
        else
            gemm_stream<1, false>(bf_h0, bf_out0, nullptr, 10000, 512,
                                  rowBase, y * 128, 1, y, smem);
    } else if (y < 236) {
        const int yt = y - 79;
        if (yt < 156)
            gemm_stream<1, true>(bf_h1, bf_out1, nullptr, 20000, 256,
                                 rowBase, yt * 128, 2, yt, smem);
        else
            gemm_stream<1, false>(bf_h1, bf_out1, nullptr, 20000, 256,
                                  rowBase, yt * 128, 2, yt, smem);
    } else if (y < 315) {
        const int y0 = (y - 236) * 4;
        const int cnt = (313 - y0 < 4) ? (313 - y0) : 4;
        gemm_resident<2>(bf_h2, bf_out2, 40000, rowBase, y0, cnt, 3, smem);
    } else {
        const int y0 = (y - 315) * 8;
        const int cnt = (157 - y0 < 8) ? (157 - y0) : 8;
        gemm_resident<1>(bf_h3, bf_out3, 20000, rowBase, y0, cnt, 4, smem);
    }
}

// ---------------------------------------------------------------- cvt (fused)
__global__ void cvt_all(const float* s0, const float* s1, const float* s2,
                        const float* s3, const float* s4, const float* s5,
                        const float* s6, const float* s7, const float* s8,
                        const float* s9)
{
    const int cum[11] = {0, 262144, 2823168, 4103168, 5383168, 6663168,
                         6983168, 7114240, 7179776, 7212544, 7228928};
    for (int i = blockIdx.x * blockDim.x + threadIdx.x; i < 7228928;
         i += gridDim.x * blockDim.x) {
        int seg = 0;
#pragma unroll
        for (int t = 1; t < 10; t++) seg += (i >= cum[t]);
        const int off = i - cum[seg];
        const float* src;
        __nv_bfloat16* dst;
        switch (seg) {
            case 0: src = s0; dst = bf_feat;  break;
            case 1: src = s1; dst = bf_headW; break;
            case 2: src = s2; dst = bf_out0;  break;
            case 3: src = s3; dst = bf_out1;  break;
            case 4: src = s4; dst = bf_out2;  break;
            case 5: src = s5; dst = bf_out3;  break;
            case 6: src = s6; dst = bf_proj0; break;
            case 7: src = s7; dst = bf_proj1; break;
            case 8: src = s8; dst = bf_proj2; break;
            default: src = s9; dst = bf_proj3; break;
        }
        const float4 v = ((const float4*)src)[off];
        __nv_bfloat162* p = (__nv_bfloat162*)dst + off * 2;
        p[0] = __floats2bfloat162_rn(v.x, v.y);
        p[1] = __floats2bfloat162_rn(v.z, v.w);
    }
}

// ---------------------------------------------------------------- small kernels
__global__ void init_kernel(const void* tgt, const void* msk) {
    const int tid = threadIdx.x;
    if (tid < B_ROWS) { g_num[tid] = 0.f; g_den[tid] = 0.f; }
    if (tid == 0) {
        const int* ti = (const int*)tgt;
        int nz = 0;
        for (int j = 0; j < 128; j++) nz += (ti[2 * j + 1] != 0);
        g_flags[0] = (nz <= 8) ? 1 : 0;
        const unsigned int* mw = (const unsigned int*)msk;
        int looks_i32 = 1;
        for (int j = 0; j < 64; j++) if (mw[j] > 255u) looks_i32 = 0;
        g_flags[1] = looks_i32;
    }
}

__global__ void combine_kernel() {
    int row = blockIdx.x, mat = blockIdx.y, lane = threadIdx.x;
    int chunks = d_chunks[mat];
    const float* pm = g_pm + d_pbase[mat] + (size_t)row * chunks;
    const float* ps = g_ps + d_pbase[mat] + (size_t)row * chunks;
    float m = -INFINITY, s = 0.f;
    for (int c = lane; c < chunks; c += 32) {
        float mo = pm[c], so = ps[c];
        float M2 = fmaxf(m, mo);
        if (M2 == -INFINITY) { m = M2; s = 0.f; }
        else { s = s * __expf(m - M2) + so * __expf(mo - M2); m = M2; }
    }
    for (int o = 1; o < 32; o <<= 1) {
        float mo = __shfl_xor_sync(0xffffffffu, m, o);
        float so = __shfl_xor_sync(0xffffffffu, s, o);
        float M2 = fmaxf(m, mo);
        if (M2 == -INFINITY) { m = M2; s = 0.f; }
        else { s = s * __expf(m - M2) + so * __expf(mo - M2); m = M2; }
    }
    if (lane == 0) g_lse[mat * B_ROWS + row] = m + logf(s);
}

// warp per target; bf16 operands (L2-warm), fp32 accumulate
__global__ void loss_kernel(const float* __restrict__ discard,
                            const void* __restrict__ tgt,
                            const void* __restrict__ msk)
{
    int gwarp = (blockIdx.x * blockDim.x + threadIdx.x) >> 5;
    int lane  = threadIdx.x & 31;
    if (gwarp >= B_ROWS * 128) return;
    int b = gwarp >> 7;

    long long v;
    if (g_flags[0]) v = ((const long long*)tgt)[gwarp];
    else            v = (long long)((const int*)tgt)[gwarp];

    float mk;
    if (g_flags[1]) mk = (((const int*)msk)[gwarp] != 0) ? 1.f : 0.f;
    else            mk = (((const unsigned char*)msk)[gwarp] != 0) ? 1.f : 0.f;

    const __nv_bfloat16 *a, *w;
    int Kd; float lse, extra;
    float hlse = g_lse[b];
    if (v < 10000) {
        a = bf_feat + (size_t)b * 1024; w = bf_headW + (size_t)v * 1024;
        Kd = 1024; lse = hlse; extra = 0.f;
    } else if (v < 20000) {
        a = bf_h0 + (size_t)b * 512; w = bf_out0 + (size_t)(v - 10000) * 512;
        Kd = 512; lse = g_lse[1 * B_ROWS + b]; extra = g_tail[b * 4 + 0] - hlse;
    } else if (v < 40000) {
        a = bf_h1 + (size_t)b * 256; w = bf_out1 + (size_t)(v - 20000) * 256;
        Kd = 256; lse = g_lse[2 * B_ROWS + b]; extra = g_tail[b * 4 + 1] - hlse;
    } else if (v < 80000) {
        a = bf_h2 + (size_t)b * 128; w = bf_out2 + (size_t)(v - 40000) * 128;
        Kd = 128; lse = g_lse[3 * B_ROWS + b]; extra = g_tail[b * 4 + 2] - hlse;
    } else {
        a = bf_h3 + (size_t)b * 64; w = bf_out3 + (size_t)(v - 80000) * 64;
        Kd = 64; lse = g_lse[4 * B_ROWS + b]; extra = g_tail[b * 4 + 3] - hlse;
    }

    float dot = 0.f;
    for (int k = lane * 8; k < Kd; k += 256) {
        const uint4 av = *(const uint4*)(a + k);
        const uint4 wv = *(const uint4*)(w + k);
        const uint32_t aw[4] = {av.x, av.y, av.z, av.w};
        const uint32_t ww[4] = {wv.x, wv.y, wv.z, wv.w};
#pragma unroll
        for (int j = 0; j < 4; j++) {
            const float2 af2 = __bfloat1622float2(*(const __nv_bfloat162*)&aw[j]);
            const float2 wf2 = __bfloat1622float2(*(const __nv_bfloat162*)&ww[j]);
            dot += af2.x * wf2.x + af2.y * wf2.y;
        }
    }
#pragma unroll
    for (int o = 16; o >= 1; o >>= 1) dot += __shfl_xor_sync(0xffffffffu, dot, o);

    if (lane == 0) {
        float lp = dot - lse + extra;
        float wt = (1.f - discard[v]) * mk;
        atomicAdd(&g_num[b], -lp * wt);
        atomicAdd(&g_den[b], wt);
    }
}

__global__ void final_kernel(float* out) {
    __shared__ float red[256];
    float s = 0.f;
    for (int i = threadIdx.x; i < B_ROWS; i += 256) s += g_num[i] / g_den[i];
    red[threadIdx.x] = s;
    __syncthreads();
    for (int o = 128; o >= 1; o >>= 1) {
        if (threadIdx.x < o) red[threadIdx.x] += red[threadIdx.x + o];
        __syncthreads();
    }
    if (threadIdx.x == 0)
        out[0] = (float)((double)red[0] / (1024.0 + 1e-5));
}

// ============================================================================
extern "C" void kernel_launch(void* const* d_in, const int* in_sizes, int n_in,
                              void* d_out, int out_size)
{
    const float* feat    = (const float*)d_in[0];
    const float* headW   = (const float*)d_in[1];
    const float* proj0   = (const float*)d_in[2];
    const float* out0    = (const float*)d_in[3];
    const float* proj1   = (const float*)d_in[4];
    const float* out1    = (const float*)d_in[5];
    const float* proj2   = (const float*)d_in[6];
    const float* out2    = (const float*)d_in[7];
    const float* proj3   = (const float*)d_in[8];
    const float* out3    = (const float*)d_in[9];
    const float* discard = (const float*)d_in[10];
    const void*  tgt     = d_in[11];
    const void*  msk     = d_in[12];
    float* out = (float*)d_out;

    cudaFuncSetAttribute(head_proj_kernel,
                         cudaFuncAttributeMaxDynamicSharedMemorySize, SMEM_SZ);
    cudaFuncSetAttribute(cluster_kernel,
                         cudaFuncAttributeMaxDynamicSharedMemorySize, SMEM_SZ);

    init_kernel<<<1, 1024>>>(tgt, msk);
    cvt_all<<<4096, 256>>>(feat, headW, out0, out1, out2, out3,
                           proj0, proj1, proj2, proj3);
    head_proj_kernel<<<dim3(8, 87),  256, SMEM_SZ>>>();
    cluster_kernel<<<dim3(8, 335),   256, SMEM_SZ>>>();
    combine_kernel<<<dim3(1024, 5), 32>>>();
    loss_kernel<<<16384, 256>>>(discard, tgt, msk);
    final_kernel<<<1, 256>>>(out);
}